// round 1
// baseline (speedup 1.0000x reference)
#include <cuda_runtime.h>

typedef unsigned long long ull;

// ---- packed f32x2 helpers (FFMA2 only reachable via PTX, per SASS_QUICKREF) ----
__device__ __forceinline__ ull pk2(float lo, float hi) {
    ull r; asm("mov.b64 %0,{%1,%2};" : "=l"(r) : "f"(lo), "f"(hi)); return r;
}
__device__ __forceinline__ void up2(ull a, float& x, float& y) {
    asm("mov.b64 {%0,%1},%2;" : "=f"(x), "=f"(y) : "l"(a));
}
__device__ __forceinline__ ull fma2(ull a, ull b, ull c) {
    ull d; asm("fma.rn.f32x2 %0,%1,%2,%3;" : "=l"(d) : "l"(a), "l"(b), "l"(c)); return d;
}

// Each thread processes 2 rows (20 input floats, 10 output floats).
// Element-pairs across the two rows share one f32x2 lane.
__global__ void __launch_bounds__(256) simplenn_kernel(
    const float* __restrict__ x,
    const float* __restrict__ gate,
    const float* __restrict__ w1,   // (2,64) row-major
    const float* __restrict__ b1,   // (64,)
    const float* __restrict__ w2,   // (64,1)
    const float* __restrict__ b2,   // (1,)
    float* __restrict__ out,        // (B,5)
    int npairs)
{
    // Duplicated-pair weight table: per hidden unit j, [ (u,u), (v,v), (c,c), (w,w) ] = 32B
    __shared__ __align__(16) ull wpk[64][4];

    int tid = threadIdx.x;
    if (tid < 64) {
        float u = w1[tid];        // w1[0][j]
        float v = w1[64 + tid];   // w1[1][j]
        float c = b1[tid];
        float w = w2[tid];
        wpk[tid][0] = pk2(u, u);
        wpk[tid][1] = pk2(v, v);
        wpk[tid][2] = pk2(c, c);
        wpk[tid][3] = pk2(w, w);
    }

    // argmax(gate_logits) — runtime-constant, uniform across all threads (L1/L2-cached)
    float g0 = gate[0], g1 = gate[1], g2 = gate[2], g3 = gate[3];
    int idx = 0; float best = g0;
    if (g1 > best) { best = g1; idx = 1; }
    if (g2 > best) { best = g2; idx = 2; }
    if (g3 > best) { best = g3; idx = 3; }

    __syncthreads();

    int t = blockIdx.x * 256 + tid;
    if (t >= npairs) return;

    // Load 2 rows = 20 floats, 80B per thread, 16B-aligned, fully coalesced
    float v20[20];
    const float4* xp = (const float4*)(x + (size_t)t * 20);
    #pragma unroll
    for (int q = 0; q < 5; q++) {
        float4 f = xp[q];
        v20[4*q+0] = f.x; v20[4*q+1] = f.y; v20[4*q+2] = f.z; v20[4*q+3] = f.w;
    }

    // Apply selected transform (uniform branch; MUFU-based intrinsics)
    if (idx == 1) {
        #pragma unroll
        for (int i = 0; i < 20; i++) v20[i] = __logf(v20[i]);
    } else if (idx == 2) {
        #pragma unroll
        for (int i = 0; i < 20; i++) v20[i] = __expf(v20[i]);
    } else if (idx == 3) {
        #pragma unroll
        for (int i = 0; i < 20; i++) v20[i] = __sinf(v20[i]);
    }

    // Pack: lane pair i holds element i of row0 (lo) and row1 (hi).
    // A = wi (sel[:, i]), B = pi (sel[:, 5+i])
    ull A[5], Bp[5], acc[5];
    float bias = b2[0];
    ull bias2 = pk2(bias, bias);
    #pragma unroll
    for (int i = 0; i < 5; i++) {
        A[i]   = pk2(v20[i],      v20[10 + i]);
        Bp[i]  = pk2(v20[5 + i],  v20[15 + i]);
        acc[i] = bias2;  // fold b2 into the accumulator
    }

    // 64 hidden units; 2x LDS.128 broadcast + 15 FFMA2 + 10 FMNMX per unit
    #pragma unroll 8
    for (int j = 0; j < 64; j++) {
        const ulonglong2* wp = (const ulonglong2*)wpk[j];
        ulonglong2 p0 = wp[0];   // (uu, vv)
        ulonglong2 p1 = wp[1];   // (cc, ww)
        ull uu = p0.x, vv = p0.y, cc = p1.x, ww = p1.y;
        #pragma unroll
        for (int i = 0; i < 5; i++) {
            ull t2 = fma2(A[i], uu, fma2(Bp[i], vv, cc));
            float h0, h1;
            up2(t2, h0, h1);
            h0 = fmaxf(h0, 0.0f);   // FMNMX on alu pipe, overlaps fma pipe
            h1 = fmaxf(h1, 0.0f);
            acc[i] = fma2(pk2(h0, h1), ww, acc[i]);
        }
    }

    // Unpack and store 10 contiguous floats (8B-aligned -> 5x st.v2)
    float r0[5], r1[5];
    #pragma unroll
    for (int i = 0; i < 5; i++) up2(acc[i], r0[i], r1[i]);

    float2* op = (float2*)(out + (size_t)t * 10);
    op[0] = make_float2(r0[0], r0[1]);
    op[1] = make_float2(r0[2], r0[3]);
    op[2] = make_float2(r0[4], r1[0]);
    op[3] = make_float2(r1[1], r1[2]);
    op[4] = make_float2(r1[3], r1[4]);
}

extern "C" void kernel_launch(void* const* d_in, const int* in_sizes, int n_in,
                              void* d_out, int out_size) {
    const float* x    = (const float*)d_in[0];
    const float* gate = (const float*)d_in[1];
    const float* w1   = (const float*)d_in[2];
    const float* b1   = (const float*)d_in[3];
    const float* w2   = (const float*)d_in[4];
    const float* b2   = (const float*)d_in[5];
    float* out = (float*)d_out;

    int nrows  = in_sizes[0] / 10;   // BATCH
    int npairs = nrows / 2;          // 2 rows per thread (BATCH is even)
    int blocks = (npairs + 255) / 256;

    simplenn_kernel<<<blocks, 256>>>(x, gate, w1, b1, w2, b2, out, npairs);
}